// round 4
// baseline (speedup 1.0000x reference)
#include <cuda_runtime.h>
#include <cuda_bf16.h>

#define BB 8
#define NN 2048
#define DD 64
#define TI 64
#define TJ 64
#define SPLIT 4
#define JT_PER_SPLIT (NN / TJ / SPLIT)   // 8 j-tiles per split

// __device__ scratch (no allocations allowed)
__device__ float g_h[BB * NN * DD];        // h_ope, fp32
__device__ float g_s[BB * NN];             // exp(a_src)
__device__ float g_t[BB * NN];             // exp(a_dst)
__device__ float g_u[BB * NN];             // exp(0.2*a_src)
__device__ float g_v[BB * NN];             // exp(0.2*a_dst)
__device__ float g_lam[2 * DD];            // lambda_adj[64], lambda_job[64]

// split-K partial results
__device__ float g_accA[SPLIT][BB * NN * DD];
__device__ float g_accJ[SPLIT][BB * NN * DD];
__device__ float g_denA[SPLIT][BB * NN];
__device__ float g_denJ[SPLIT][BB * NN];

// ---- packed f32x2 helpers (Blackwell FFMA2) ----
__device__ __forceinline__ unsigned long long splat2(float x) {
    unsigned long long r;
    asm("mov.b64 %0, {%1, %1};" : "=l"(r) : "f"(x));
    return r;
}
__device__ __forceinline__ void fma2(unsigned long long& d, unsigned long long a, unsigned long long b) {
    asm("fma.rn.f32x2 %0, %1, %2, %0;" : "+l"(d) : "l"(a), "l"(b));
}
__device__ __forceinline__ float2 unpack2(unsigned long long v) {
    float2 f;
    asm("mov.b64 {%0, %1}, %2;" : "=f"(f.x), "=f"(f.y) : "l"(v));
    return f;
}

union F4U2 { float4 f; unsigned long long u[2]; };

// =====================================================================
// Kernel A: h = feats @ W^T, a_src/a_dst exps, lambdas
// 512 threads, 8 rows/block. Conflict-free smem (pitch 65), shuffle reduce.
// =====================================================================
__global__ __launch_bounds__(512) void prep_kernel(
    const float* __restrict__ feats, const float* __restrict__ W,
    const float* __restrict__ attn_src, const float* __restrict__ attn_dst,
    const float* __restrict__ lambda_params)
{
    __shared__ float sWt[DD * 65];   // sWt[d*65+o] = W[o][d]
    __shared__ float sF[8][DD];
    __shared__ float sRs[16], sRd[16];

    const int t = threadIdx.x;
    const int o = t & 63;
    const int r = t >> 6;
    const int row0 = blockIdx.x * 8;

    #pragma unroll
    for (int w = 0; w < 8; ++w) {
        int x = t + 512 * w;
        sWt[(x & 63) * 65 + (x >> 6)] = W[x];   // pitch 65: conflict-free
    }
    sF[r][o] = feats[(size_t)(row0 + r) * DD + o];
    __syncthreads();

    float h = 0.0f;
    #pragma unroll
    for (int d = 0; d < DD; ++d) h = fmaf(sF[r][d], sWt[d * 65 + o], h);

    g_h[(size_t)(row0 + r) * DD + o] = h;

    float rs = h * attn_src[o];
    float rd = h * attn_dst[o];
    #pragma unroll
    for (int off = 16; off; off >>= 1) {
        rs += __shfl_down_sync(0xffffffffu, rs, off);
        rd += __shfl_down_sync(0xffffffffu, rd, off);
    }
    const int w = t >> 5;
    if ((t & 31) == 0) { sRs[w] = rs; sRd[w] = rd; }
    __syncthreads();

    if (t < 8) {
        float as = sRs[2 * t] + sRs[2 * t + 1];
        float ad = sRd[2 * t] + sRd[2 * t + 1];
        int n = row0 + t;
        g_s[n] = expf(as);
        g_u[n] = expf(0.2f * as);
        g_t[n] = expf(ad);
        g_v[n] = expf(0.2f * ad);
    }
    if (blockIdx.x == 0 && t >= 64 && t < 128) {
        int d = t - 64;
        float l0 = lambda_params[d * 2];
        float l1 = lambda_params[d * 2 + 1];
        float m = fmaxf(l0, l1);
        float e0 = expf(l0 - m), e1 = expf(l1 - m);
        float inv = 1.0f / (e0 + e1);
        g_lam[d] = e0 * inv;
        g_lam[DD + d] = e1 * inv;
    }
}

// =====================================================================
// Kernel B: split-K masked softmax partial sums, ONE mask per block.
// grid = (N/TI, B, 2*SPLIT): z = sp*2 + maskSel
// 128 threads; thread tile = 4i x 8d, FFMA2 packed over d-pairs.
// =====================================================================
__global__ __launch_bounds__(128, 6) void attn_split_kernel(
    const int* __restrict__ mask_adj, const int* __restrict__ mask_job,
    const int* __restrict__ bidx)
{
    __shared__ float sP[TJ * TI];     // sP[j][i], 4-float groups XOR-swizzled
    __shared__ float sSi[TI], sUi[TI];

    const int t = threadIdx.x;
    const int b = blockIdx.y;
    const int z = blockIdx.z;
    const int sp = z >> 1;
    const int isJob = z & 1;
    const int i_base = blockIdx.x * TI;
    const int bN = b * NN;

    // batch_idxes is arange(B) (identity gather); clamp defensively
    int mb = bidx[b];
    if (mb < 0 || mb >= BB) mb = b;

    const int* __restrict__ mask = isJob ? mask_job : mask_adj;
    float* __restrict__ accOut = isJob ? g_accJ[sp] : g_accA[sp];
    float* __restrict__ denOut = isJob ? g_denJ[sp] : g_denA[sp];

    // phase-2 identity
    const int dg = t & 7;    // d-group: d = dg*8..+7
    const int ig = t >> 3;   // i-group: i = ig*4..+3  (0..15)
    // phase-1 identity
    const int jj = t & 63;
    const int kh = t >> 6;   // 0/1

    if (t < TI) {
        sSi[t] = g_s[bN + i_base + t];
        sUi[t] = g_u[bN + i_base + t];
    }

    const int* maB = mask + ((size_t)mb * NN + i_base) * NN;

    unsigned long long acc[16];      // [c][dp]: c = i offset 0..3, dp = d-pair 0..3
    #pragma unroll
    for (int q = 0; q < 16; ++q) acc[q] = 0ull;
    float den0 = 0.f, den1 = 0.f, den2 = 0.f, den3 = 0.f;

    const int jt0 = sp * JT_PER_SPLIT;
    for (int jt = jt0; jt < jt0 + JT_PER_SPLIT; ++jt) {
        const int jb = jt * TJ;
        __syncthreads();   // previous phase-2 reads done (also covers sSi init)

        // ---- phase 1: build masked P tile (one mask) ----
        const float tj = g_t[bN + jb + jj];
        const float vj = g_v[bN + jb + jj];
        const int* mP = maB + jb + jj;
        #pragma unroll
        for (int gi = 0; gi < 8; ++gi) {
            const int g = gi * 2 + kh;     // i-group 0..15
            const int i0 = g * 4;
            const int m0 = mP[(i0 + 0) * NN];
            const int m1 = mP[(i0 + 1) * NN];
            const int m2 = mP[(i0 + 2) * NN];
            const int m3 = mP[(i0 + 3) * NN];
            // exp(leaky(e)): e>=0 <=> s*t>=1
            const float st0 = sSi[i0 + 0] * tj, uv0 = sUi[i0 + 0] * vj;
            const float st1 = sSi[i0 + 1] * tj, uv1 = sUi[i0 + 1] * vj;
            const float st2 = sSi[i0 + 2] * tj, uv2 = sUi[i0 + 2] * vj;
            const float st3 = sSi[i0 + 3] * tj, uv3 = sUi[i0 + 3] * vj;
            float4 p;
            p.x = m0 ? ((st0 >= 1.0f) ? st0 : uv0) : 0.0f;
            p.y = m1 ? ((st1 >= 1.0f) ? st1 : uv1) : 0.0f;
            p.z = m2 ? ((st2 >= 1.0f) ? st2 : uv2) : 0.0f;
            p.w = m3 ? ((st3 >= 1.0f) ? st3 : uv3) : 0.0f;
            *(float4*)&sP[jj * TI + ((g ^ (jj & 15)) << 2)] = p;
        }
        __syncthreads();

        // ---- phase 2: acc += P^T * h, d-pair packed ----
        const float4* hB = (const float4*)(g_h + ((size_t)(bN + jb) << 6)) + (dg << 1);
        #pragma unroll 2
        for (int j = 0; j < TJ; ++j) {
            const float4 p4 = *(const float4*)&sP[j * TI + ((ig ^ (j & 15)) << 2)];
            F4U2 h0, h1;
            h0.f = hB[j * 16];
            h1.f = hB[j * 16 + 1];
            const unsigned long long P0 = splat2(p4.x);
            const unsigned long long P1 = splat2(p4.y);
            const unsigned long long P2 = splat2(p4.z);
            const unsigned long long P3 = splat2(p4.w);
            fma2(acc[0],  P0, h0.u[0]); fma2(acc[1],  P0, h0.u[1]);
            fma2(acc[2],  P0, h1.u[0]); fma2(acc[3],  P0, h1.u[1]);
            fma2(acc[4],  P1, h0.u[0]); fma2(acc[5],  P1, h0.u[1]);
            fma2(acc[6],  P1, h1.u[0]); fma2(acc[7],  P1, h1.u[1]);
            fma2(acc[8],  P2, h0.u[0]); fma2(acc[9],  P2, h0.u[1]);
            fma2(acc[10], P2, h1.u[0]); fma2(acc[11], P2, h1.u[1]);
            fma2(acc[12], P3, h0.u[0]); fma2(acc[13], P3, h0.u[1]);
            fma2(acc[14], P3, h1.u[0]); fma2(acc[15], P3, h1.u[1]);
            if (dg == 0) { den0 += p4.x; den1 += p4.y; den2 += p4.z; den3 += p4.w; }
        }
    }

    // ---- epilogue: write partial sums ----
    if (dg == 0) {
        const int nb = bN + i_base + ig * 4;
        denOut[nb + 0] = den0;
        denOut[nb + 1] = den1;
        denOut[nb + 2] = den2;
        denOut[nb + 3] = den3;
    }
    #pragma unroll
    for (int c = 0; c < 4; ++c) {
        const size_t off = ((size_t)(bN + i_base + ig * 4 + c) << 6) + dg * 8;
        const float2 a0 = unpack2(acc[c * 4 + 0]);
        const float2 a1 = unpack2(acc[c * 4 + 1]);
        const float2 a2 = unpack2(acc[c * 4 + 2]);
        const float2 a3 = unpack2(acc[c * 4 + 3]);
        *(float4*)(accOut + off)     = make_float4(a0.x, a0.y, a1.x, a1.y);
        *(float4*)(accOut + off + 4) = make_float4(a2.x, a2.y, a3.x, a3.y);
    }
}

// =====================================================================
// Kernel C: combine splits, normalize, blend, residual
// =====================================================================
__global__ __launch_bounds__(256) void combine_kernel(
    const float* __restrict__ feats, float* __restrict__ out)
{
    const int idx4 = blockIdx.x * blockDim.x + threadIdx.x;
    const int idx = idx4 * 4;
    const int n = idx >> 6;
    const int d = idx & 63;

    float4 na = make_float4(0.f, 0.f, 0.f, 0.f);
    float4 nj = make_float4(0.f, 0.f, 0.f, 0.f);
    float da = 0.f, dj = 0.f;
    #pragma unroll
    for (int sp = 0; sp < SPLIT; ++sp) {
        const float4 a = *(const float4*)(g_accA[sp] + idx);
        const float4 j = *(const float4*)(g_accJ[sp] + idx);
        na.x += a.x; na.y += a.y; na.z += a.z; na.w += a.w;
        nj.x += j.x; nj.y += j.y; nj.z += j.z; nj.w += j.w;
        da += g_denA[sp][n];
        dj += g_denJ[sp][n];
    }
    const float ra = 1.0f / da;
    const float rj = 1.0f / dj;
    const float4 lA = *(const float4*)&g_lam[d];
    const float4 lJ = *(const float4*)&g_lam[DD + d];
    const float4 f = *(const float4*)(feats + idx);
    float4 o;
    o.x = lA.x * na.x * ra + lJ.x * nj.x * rj + f.x;
    o.y = lA.y * na.y * ra + lJ.y * nj.y * rj + f.y;
    o.z = lA.z * na.z * ra + lJ.z * nj.z * rj + f.z;
    o.w = lA.w * na.w * ra + lJ.w * nj.w * rj + f.w;
    *(float4*)(out + idx) = o;
}

extern "C" void kernel_launch(void* const* d_in, const int* in_sizes, int n_in,
                              void* d_out, int out_size) {
    (void)in_sizes; (void)n_in; (void)out_size;
    const int*   mask_adj      = (const int*)d_in[0];
    const int*   mask_job      = (const int*)d_in[1];
    const int*   bidx          = (const int*)d_in[2];
    const float* feats         = (const float*)d_in[3];
    const float* W             = (const float*)d_in[4];
    const float* attn_src      = (const float*)d_in[5];
    const float* attn_dst      = (const float*)d_in[6];
    const float* lambda_params = (const float*)d_in[7];
    float* out = (float*)d_out;

    prep_kernel<<<BB * NN / 8, 512>>>(feats, W, attn_src, attn_dst, lambda_params);
    attn_split_kernel<<<dim3(NN / TI, BB, 2 * SPLIT), 128>>>(mask_adj, mask_job, bidx);
    combine_kernel<<<BB * NN * DD / 4 / 256, 256>>>(feats, out);
}

// round 6
// speedup vs baseline: 3.2078x; 3.2078x over previous
#include <cuda_runtime.h>
#include <cuda_bf16.h>
#include <cstdint>

#define BB 8
#define NN 2048
#define DD 64
#define TIM 64               // i-rows per CTA (4 warps x 16)
#define KC 64                // j-chunk
#define NCHUNK (NN / KC)     // 32
#define PITCH 144            // smem H row pitch (bytes): conflict-free ldmatrix

// ---- device scratch ----
__device__ __nv_bfloat16 g_hb[BB * NN * DD];  // H: [n][d] bf16
__device__ float g_s[BB * NN];                // exp(a_src)
__device__ float g_t[BB * NN];                // exp(a_dst)
__device__ float g_u[BB * NN];                // exp(0.2*a_src)
__device__ float g_v[BB * NN];                // exp(0.2*a_dst)
__device__ float g_lam[2 * DD];               // lambda_adj[64], lambda_job[64]

// ---- PTX helpers (all base-target instructions: sm_80/75) ----
__device__ __forceinline__ void mma_bf16(float* d,
    uint32_t a0, uint32_t a1, uint32_t a2, uint32_t a3, uint32_t b0, uint32_t b1) {
    asm volatile(
        "mma.sync.aligned.m16n8k16.row.col.f32.bf16.bf16.f32 "
        "{%0,%1,%2,%3}, {%4,%5,%6,%7}, {%8,%9}, {%0,%1,%2,%3};"
        : "+f"(d[0]), "+f"(d[1]), "+f"(d[2]), "+f"(d[3])
        : "r"(a0), "r"(a1), "r"(a2), "r"(a3), "r"(b0), "r"(b1));
}
__device__ __forceinline__ void ldsm4t(uint32_t& r0, uint32_t& r1, uint32_t& r2, uint32_t& r3, uint32_t addr) {
    asm volatile("ldmatrix.sync.aligned.m8n8.x4.trans.shared.b16 {%0,%1,%2,%3}, [%4];"
        : "=r"(r0), "=r"(r1), "=r"(r2), "=r"(r3) : "r"(addr));
}
__device__ __forceinline__ uint32_t packbf(float lo, float hi) {
    uint32_t r;
    asm("cvt.rn.satfinite.bf16x2.f32 %0, %1, %2;" : "=r"(r) : "f"(hi), "f"(lo));
    return r;
}
#define CP16(dst, src) asm volatile("cp.async.cg.shared.global [%0], [%1], 16;" :: "r"(dst), "l"(src))
#define CP_COMMIT()    asm volatile("cp.async.commit_group;" ::: "memory")
#define CP_WAIT0()     asm volatile("cp.async.wait_group 0;" ::: "memory")

__device__ __forceinline__ float pvsel(float st, float uv) { return (st >= 1.0f) ? st : uv; }

// =====================================================================
// Kernel A: h = feats @ W^T (bf16 out), exps of a_src/a_dst, lambdas
// =====================================================================
__global__ __launch_bounds__(512) void prep_kernel(
    const float* __restrict__ feats, const float* __restrict__ W,
    const float* __restrict__ attn_src, const float* __restrict__ attn_dst,
    const float* __restrict__ lambda_params)
{
    __shared__ float sWt[DD * 65];   // sWt[d*65+o] = W[o][d]
    __shared__ float sF[8][DD];
    __shared__ float sRs[16], sRd[16];

    const int t = threadIdx.x;
    const int o = t & 63;
    const int r = t >> 6;
    const int row0 = blockIdx.x * 8;

    #pragma unroll
    for (int w = 0; w < 8; ++w) {
        int x = t + 512 * w;
        sWt[(x & 63) * 65 + (x >> 6)] = W[x];
    }
    sF[r][o] = feats[(size_t)(row0 + r) * DD + o];
    __syncthreads();

    float h = 0.0f;
    #pragma unroll
    for (int d = 0; d < DD; ++d) h = fmaf(sF[r][d], sWt[d * 65 + o], h);

    g_hb[(size_t)(row0 + r) * DD + o] = __float2bfloat16(h);

    float rs = h * attn_src[o];
    float rd = h * attn_dst[o];
    #pragma unroll
    for (int off = 16; off; off >>= 1) {
        rs += __shfl_down_sync(0xffffffffu, rs, off);
        rd += __shfl_down_sync(0xffffffffu, rd, off);
    }
    if ((t & 31) == 0) { sRs[t >> 5] = rs; sRd[t >> 5] = rd; }
    __syncthreads();

    if (t < 8) {
        float as = sRs[2 * t] + sRs[2 * t + 1];
        float ad = sRd[2 * t] + sRd[2 * t + 1];
        int n = row0 + t;
        g_s[n] = expf(as);
        g_u[n] = expf(0.2f * as);
        g_t[n] = expf(ad);
        g_v[n] = expf(0.2f * ad);
    }
    if (blockIdx.x == 0 && t >= 64 && t < 128) {
        int d = t - 64;
        float l0 = lambda_params[d * 2];
        float l1 = lambda_params[d * 2 + 1];
        float m = fmaxf(l0, l1);
        float e0 = expf(l0 - m), e1 = expf(l1 - m);
        float inv = 1.0f / (e0 + e1);
        g_lam[d] = e0 * inv;
        g_lam[DD + d] = e1 * inv;
    }
}

// =====================================================================
// Kernel B: HMMA fused dual-masked softmax attention
// grid = (NN/TIM=32, BB=8) = 256 CTAs, 128 threads (4 warps x 16 rows)
// =====================================================================
__global__ __launch_bounds__(128) void attn_hmma_kernel(
    const int* __restrict__ mask_adj, const int* __restrict__ mask_job,
    const int* __restrict__ bidx,
    const float* __restrict__ feats, float* __restrict__ out)
{
    __shared__ __align__(16) char  sH[2][KC * PITCH];   // H chunk, bf16 rows (128B used, 144B pitch)
    __shared__ __align__(16) float sT[2][KC], sV[2][KC];
    __shared__ float sLamA[DD], sLamJ[DD];

    const int t = threadIdx.x;
    const int lane = t & 31, wid = t >> 5;
    const int b = blockIdx.y;
    const int i_base = blockIdx.x * TIM;
    const int bN = b * NN;

    int mb = bidx[b];                 // arange(B) identity gather; clamp defensively
    if (mb < 0 || mb >= BB) mb = b;

    if (t < DD) { sLamA[t] = g_lam[t]; sLamJ[t] = g_lam[DD + t]; }

    const int g  = lane >> 2;
    const int tq = lane & 3;
    const int r0 = wid * 16 + g;      // row in tile (0..63)
    const int r1 = r0 + 8;

    const float si0 = g_s[bN + i_base + r0], ui0 = g_u[bN + i_base + r0];
    const float si1 = g_s[bN + i_base + r1], ui1 = g_u[bN + i_base + r1];

    const int* pa0 = mask_adj + ((size_t)mb * NN + i_base + r0) * NN;
    const int* pa1 = pa0 + (size_t)8 * NN;
    const int* pj0 = mask_job + ((size_t)mb * NN + i_base + r0) * NN;
    const int* pj1 = pj0 + (size_t)8 * NN;

    const uint32_t shb0 = (uint32_t)__cvta_generic_to_shared(&sH[0][0]);
    const uint32_t shb1 = (uint32_t)__cvta_generic_to_shared(&sH[1][0]);
    const uint32_t stb0 = (uint32_t)__cvta_generic_to_shared(&sT[0][0]);
    const uint32_t stb1 = (uint32_t)__cvta_generic_to_shared(&sT[1][0]);
    const uint32_t svb0 = (uint32_t)__cvta_generic_to_shared(&sV[0][0]);
    const uint32_t svb1 = (uint32_t)__cvta_generic_to_shared(&sV[1][0]);

    // ldmatrix per-lane offset: mid 0..3 -> (khalf, n-odd); mrow = row within 8x8
    const int mid = lane >> 3, mrow = lane & 7;
    const int lmoff = ((mid & 1) * 8 + mrow) * PITCH + (mid >> 1) * 16;

    // async stage of chunk c into buffer s
    auto stage = [&](int c, int s) {
        const char* hsrc = (const char*)(g_hb + ((size_t)(bN + c * KC) << 6));
        const int row = t >> 1, seg = t & 1;
        const uint32_t d = (s ? shb1 : shb0) + row * PITCH + seg * 64;
        const char* gp = hsrc + row * 128 + seg * 64;
        CP16(d,      gp);
        CP16(d + 16, gp + 16);
        CP16(d + 32, gp + 32);
        CP16(d + 48, gp + 48);
        if (t < 16) {
            CP16((s ? stb1 : stb0) + t * 16, (const char*)(g_t + bN + c * KC) + t * 16);
        } else if (t < 32) {
            CP16((s ? svb1 : svb0) + (t - 16) * 16, (const char*)(g_v + bN + c * KC) + (t - 16) * 16);
        }
    };

    float accA[32], accJ[32];
    #pragma unroll
    for (int q = 0; q < 32; ++q) { accA[q] = 0.f; accJ[q] = 0.f; }
    float denA0 = 0.f, denA1 = 0.f, denJ0 = 0.f, denJ1 = 0.f;

    stage(0, 0);
    CP_COMMIT();

    for (int c = 0; c < NCHUNK; ++c) {
        const int s = c & 1;
        CP_WAIT0();
        __syncthreads();                       // buffer s ready; prev compute done
        if (c + 1 < NCHUNK) { stage(c + 1, 1 - s); CP_COMMIT(); }

        const int jb = c * KC;
        const uint32_t hbase = (s ? shb1 : shb0) + lmoff;
        const float* sTs = sT[s];
        const float* sVs = sV[s];

        #pragma unroll
        for (int kt = 0; kt < 4; ++kt) {
            const int jl = kt * 16;
            const float2 tlo = *(const float2*)&sTs[jl + 2 * tq];
            const float2 thi = *(const float2*)&sTs[jl + 2 * tq + 8];
            const float2 vlo = *(const float2*)&sVs[jl + 2 * tq];
            const float2 vhi = *(const float2*)&sVs[jl + 2 * tq + 8];
            const int off_lo = jb + jl + 2 * tq;
            const int off_hi = off_lo + 8;
            const int2 ma00 = *(const int2*)(pa0 + off_lo);
            const int2 ma0h = *(const int2*)(pa0 + off_hi);
            const int2 ma10 = *(const int2*)(pa1 + off_lo);
            const int2 ma1h = *(const int2*)(pa1 + off_hi);
            const int2 mj00 = *(const int2*)(pj0 + off_lo);
            const int2 mj0h = *(const int2*)(pj0 + off_hi);
            const int2 mj10 = *(const int2*)(pj1 + off_lo);
            const int2 mj1h = *(const int2*)(pj1 + off_hi);

            // pre-mask p values: exp(leaky(e)) = st if st>=1 else uv
            const float pv00 = pvsel(si0 * tlo.x, ui0 * vlo.x);
            const float pv01 = pvsel(si0 * tlo.y, ui0 * vlo.y);
            const float pv0h0 = pvsel(si0 * thi.x, ui0 * vhi.x);
            const float pv0h1 = pvsel(si0 * thi.y, ui0 * vhi.y);
            const float pv10 = pvsel(si1 * tlo.x, ui1 * vlo.x);
            const float pv11 = pvsel(si1 * tlo.y, ui1 * vlo.y);
            const float pv1h0 = pvsel(si1 * thi.x, ui1 * vhi.x);
            const float pv1h1 = pvsel(si1 * thi.y, ui1 * vhi.y);

            const float A00 = ma00.x ? pv00 : 0.f,  A01 = ma00.y ? pv01 : 0.f;
            const float A0h0 = ma0h.x ? pv0h0 : 0.f, A0h1 = ma0h.y ? pv0h1 : 0.f;
            const float A10 = ma10.x ? pv10 : 0.f,  A11 = ma10.y ? pv11 : 0.f;
            const float A1h0 = ma1h.x ? pv1h0 : 0.f, A1h1 = ma1h.y ? pv1h1 : 0.f;
            const float J00 = mj00.x ? pv00 : 0.f,  J01 = mj00.y ? pv01 : 0.f;
            const float J0h0 = mj0h.x ? pv0h0 : 0.f, J0h1 = mj0h.y ? pv0h1 : 0.f;
            const float J10 = mj10.x ? pv10 : 0.f,  J11 = mj10.y ? pv11 : 0.f;
            const float J1h0 = mj1h.x ? pv1h0 : 0.f, J1h1 = mj1h.y ? pv1h1 : 0.f;

            denA0 += (A00 + A01) + (A0h0 + A0h1);
            denA1 += (A10 + A11) + (A1h0 + A1h1);
            denJ0 += (J00 + J01) + (J0h0 + J0h1);
            denJ1 += (J10 + J11) + (J1h0 + J1h1);

            // A fragments (m16n8k16 layout): rows {g, g+8}, k = {2t,2t+1, 2t+8,2t+9}
            const uint32_t aA0 = packbf(A00, A01),   aA1 = packbf(A10, A11);
            const uint32_t aA2 = packbf(A0h0, A0h1), aA3 = packbf(A1h0, A1h1);
            const uint32_t aJ0 = packbf(J00, J01),   aJ1 = packbf(J10, J11);
            const uint32_t aJ2 = packbf(J0h0, J0h1), aJ3 = packbf(J1h0, J1h1);

            const uint32_t hb = hbase + kt * (16 * PITCH);
            #pragma unroll
            for (int np = 0; np < 4; ++np) {
                uint32_t b0, b1, b2, b3;
                ldsm4t(b0, b1, b2, b3, hb + np * 32);
                mma_bf16(&accA[(2 * np) * 4],     aA0, aA1, aA2, aA3, b0, b1);
                mma_bf16(&accA[(2 * np + 1) * 4], aA0, aA1, aA2, aA3, b2, b3);
                mma_bf16(&accJ[(2 * np) * 4],     aJ0, aJ1, aJ2, aJ3, b0, b1);
                mma_bf16(&accJ[(2 * np + 1) * 4], aJ0, aJ1, aJ2, aJ3, b2, b3);
            }
        }
    }

    // denominator butterfly over the 4 lanes sharing g
    denA0 += __shfl_xor_sync(0xffffffffu, denA0, 1);
    denA0 += __shfl_xor_sync(0xffffffffu, denA0, 2);
    denA1 += __shfl_xor_sync(0xffffffffu, denA1, 1);
    denA1 += __shfl_xor_sync(0xffffffffu, denA1, 2);
    denJ0 += __shfl_xor_sync(0xffffffffu, denJ0, 1);
    denJ0 += __shfl_xor_sync(0xffffffffu, denJ0, 2);
    denJ1 += __shfl_xor_sync(0xffffffffu, denJ1, 1);
    denJ1 += __shfl_xor_sync(0xffffffffu, denJ1, 2);
    const float iA0 = 1.0f / denA0, iA1 = 1.0f / denA1;
    const float iJ0 = 1.0f / denJ0, iJ1 = 1.0f / denJ1;

    // epilogue: normalize + lambda blend + residual
    const float* f0 = feats + ((size_t)(bN + i_base + r0) << 6);
    const float* f1 = feats + ((size_t)(bN + i_base + r1) << 6);
    float* o0 = out + ((size_t)(bN + i_base + r0) << 6);
    float* o1 = out + ((size_t)(bN + i_base + r1) << 6);
    #pragma unroll
    for (int n = 0; n < 8; ++n) {
        const int c0 = n * 8 + 2 * tq;
        const float2 lA = *(const float2*)&sLamA[c0];
        const float2 lJ = *(const float2*)&sLamJ[c0];
        const float2 fr0 = *(const float2*)(f0 + c0);
        const float2 fr1 = *(const float2*)(f1 + c0);
        float2 q0, q1;
        q0.x = lA.x * accA[n * 4 + 0] * iA0 + lJ.x * accJ[n * 4 + 0] * iJ0 + fr0.x;
        q0.y = lA.y * accA[n * 4 + 1] * iA0 + lJ.y * accJ[n * 4 + 1] * iJ0 + fr0.y;
        q1.x = lA.x * accA[n * 4 + 2] * iA1 + lJ.x * accJ[n * 4 + 2] * iJ1 + fr1.x;
        q1.y = lA.y * accA[n * 4 + 3] * iA1 + lJ.y * accJ[n * 4 + 3] * iJ1 + fr1.y;
        *(float2*)(o0 + c0) = q0;
        *(float2*)(o1 + c0) = q1;
    }
}

extern "C" void kernel_launch(void* const* d_in, const int* in_sizes, int n_in,
                              void* d_out, int out_size) {
    (void)in_sizes; (void)n_in; (void)out_size;
    const int*   mask_adj      = (const int*)d_in[0];
    const int*   mask_job      = (const int*)d_in[1];
    const int*   bidx          = (const int*)d_in[2];
    const float* feats         = (const float*)d_in[3];
    const float* W             = (const float*)d_in[4];
    const float* attn_src      = (const float*)d_in[5];
    const float* attn_dst      = (const float*)d_in[6];
    const float* lambda_params = (const float*)d_in[7];
    float* out = (float*)d_out;

    prep_kernel<<<BB * NN / 8, 512>>>(feats, W, attn_src, attn_dst, lambda_params);
    attn_hmma_kernel<<<dim3(NN / TIM, BB), 128>>>(mask_adj, mask_job, bidx, feats, out);
}